// round 12
// baseline (speedup 1.0000x reference)
#include <cuda_runtime.h>
#include <cuda_fp16.h>
#include <math.h>

#define B_SZ   2
#define L_SZ   2048
#define D_SZ   1024
#define H_SZ   16
#define DH     64
#define M_SZ   (B_SZ * L_SZ)   // 4096

// ---------------- scratch (device globals) ----------------
__device__ __half g_qh[M_SZ * D_SZ];
__device__ __half g_kh[M_SZ * D_SZ];
__device__ __half g_vh[M_SZ * D_SZ];
__device__ __half g_wqh[D_SZ * D_SZ];
__device__ __half g_wkh[D_SZ * D_SZ];
__device__ __half g_wvh[D_SZ * D_SZ];
__device__ __half g_woh[D_SZ * D_SZ];
__device__ __half g_qp[M_SZ * D_SZ];
__device__ __half g_kp[M_SZ * D_SZ];
__device__ __half g_vp[M_SZ * D_SZ];
__device__ __half g_ctx[M_SZ * D_SZ];

// ---------------- PTX helpers ----------------
__device__ __forceinline__ unsigned sptr(const void* p) {
    return (unsigned)__cvta_generic_to_shared(p);
}
__device__ __forceinline__ void ldsm4(unsigned& a, unsigned& b, unsigned& c, unsigned& d,
                                      unsigned addr) {
    asm volatile("ldmatrix.sync.aligned.m8n8.x4.shared.b16 {%0,%1,%2,%3}, [%4];"
                 : "=r"(a), "=r"(b), "=r"(c), "=r"(d) : "r"(addr));
}
__device__ __forceinline__ void ldsm4t(unsigned& a, unsigned& b, unsigned& c, unsigned& d,
                                       unsigned addr) {
    asm volatile("ldmatrix.sync.aligned.m8n8.x4.trans.shared.b16 {%0,%1,%2,%3}, [%4];"
                 : "=r"(a), "=r"(b), "=r"(c), "=r"(d) : "r"(addr));
}
// fp32-accumulate (attention)
__device__ __forceinline__ void mma16(float* c, const unsigned* a, unsigned b0, unsigned b1) {
    asm volatile(
        "mma.sync.aligned.m16n8k16.row.col.f32.f16.f16.f32 "
        "{%0,%1,%2,%3}, {%4,%5,%6,%7}, {%8,%9}, {%0,%1,%2,%3};"
        : "+f"(c[0]), "+f"(c[1]), "+f"(c[2]), "+f"(c[3])
        : "r"(a[0]), "r"(a[1]), "r"(a[2]), "r"(a[3]), "r"(b0), "r"(b1));
}
// fp16-accumulate (GEMM, 2x rate hypothesis): init form (C = 0)
__device__ __forceinline__ void mma16h_z(unsigned* c, const unsigned* a,
                                         unsigned b0, unsigned b1) {
    asm volatile(
        "mma.sync.aligned.m16n8k16.row.col.f16.f16.f16.f16 "
        "{%0,%1}, {%2,%3,%4,%5}, {%6,%7}, {%8,%8};"
        : "=r"(c[0]), "=r"(c[1])
        : "r"(a[0]), "r"(a[1]), "r"(a[2]), "r"(a[3]), "r"(b0), "r"(b1), "r"(0u));
}
// fp16-accumulate: accumulate form
__device__ __forceinline__ void mma16h(unsigned* c, const unsigned* a,
                                       unsigned b0, unsigned b1) {
    asm volatile(
        "mma.sync.aligned.m16n8k16.row.col.f16.f16.f16.f16 "
        "{%0,%1}, {%2,%3,%4,%5}, {%6,%7}, {%0,%1};"
        : "+r"(c[0]), "+r"(c[1])
        : "r"(a[0]), "r"(a[1]), "r"(a[2]), "r"(a[3]), "r"(b0), "r"(b1));
}
__device__ __forceinline__ void cp16(unsigned s, const void* g) {
    asm volatile("cp.async.cg.shared.global [%0], [%1], 16;" :: "r"(s), "l"(g));
}
#define CP_COMMIT asm volatile("cp.async.commit_group;")
#define CP_WAIT1  asm volatile("cp.async.wait_group 1;")

__device__ __forceinline__ unsigned pack_h2(float a, float b) {
    __half2 h = __floats2half2_rn(a, b);
    return *(unsigned*)&h;
}

// ======================================================================
// fp32 -> fp16 conversion (7 arrays in one launch)
// ======================================================================
struct F2HArgs {
    const float2* src[7];
    __half2*      dst[7];
    int           n2[7];
};

__global__ void f2h_kernel(F2HArgs p) {
    const int seg = blockIdx.y;
    const int n2 = p.n2[seg];
    const float2* s = p.src[seg];
    __half2* d = p.dst[seg];
    for (int i = blockIdx.x * blockDim.x + threadIdx.x; i < n2;
         i += gridDim.x * blockDim.x) {
        float2 v = s[i];
        d[i] = __floats2half2_rn(v.x, v.y);
    }
}

// ======================================================================
// GEMM (NT): C[m][n] = (sum_k A[m][k]*W[n][k] + bias[n]) * oscale
// R8 base config: CTA 128x128, 512 threads (16 warps, 4x4), warp 32x32,
// BK=32, 3-stage cp.async ring, stride-40 rows.
// NEW: fp16-ACCUMULATE mma (2x rate hypothesis) with per-stage (K=32)
// promotion into fp32 master accumulators -> error ~4-5e-4 added.
// blockIdx.z selects problem (Q/K/V fused).
// ======================================================================
#define GBK   32
#define GAST  40                                // halves per row
#define GROW_B (GAST * 2)                       // 80 bytes per row
#define GSTG_BYTES (256 * GROW_B)               // 20480
#define GSM_BYTES  (3 * GSTG_BYTES)             // 61440
#define NSTG  (D_SZ / GBK)                      // 32

struct GemmBatch {
    const __half* A[3];
    const __half* W[3];
    const float*  bias[3];
    void*         out[3];
    float         oscale[3];
};

template<bool OUTH>
__global__ __launch_bounds__(512)
void gemm_h(GemmBatch p)
{
    extern __shared__ __half smg[];

    const int z = blockIdx.z;
    const __half* __restrict__ A = p.A[z];
    const __half* __restrict__ W = p.W[z];
    const float*  __restrict__ bias = p.bias[z];
    const float oscale = p.oscale[z];

    const int tid  = threadIdx.x;
    const int lane = tid & 31;
    const int warp = tid >> 5;
    const int wm   = (warp >> 2) * 32;    // 0..96
    const int wn   = (warp & 3) * 32;     // 0..96
    const int g    = lane >> 2;
    const int tg   = lane & 3;
    const int m0   = blockIdx.y * 128;
    const int n0   = blockIdx.x * 128;

    // loader: 256 logical rows (A:0-127, W:128-255); row = tid>>1,
    // thread covers bytes [lck*16, +16) and [lck*16+32, +16) of the 64B row.
    const int lrow = tid >> 1;            // 0..255
    const int lck  = tid & 1;             // 0..1
    const bool isW = lrow >= 128;
    const int  grow = isW ? (lrow - 128) : lrow;

    // ldsm lane bases
    const int a_r = lane & 15;
    const int a_k = ((lane >> 4) & 1) * 8;
    const int b_n = ((lane >> 4) & 1) * 8 + (lane & 7);
    const int b_k = ((lane >> 3) & 1) * 8;

    // fp32 master accumulators (promoted once per stage)
    float acc[2][4][4];
#pragma unroll
    for (int i = 0; i < 2; i++)
#pragma unroll
        for (int j = 0; j < 4; j++)
#pragma unroll
            for (int e = 0; e < 4; e++) acc[i][j][e] = 0.0f;

    const __half* Gp = (isW ? W + (size_t)(n0 + grow) * D_SZ
                            : A + (size_t)(m0 + grow) * D_SZ) + lck * 8;
    const unsigned smb = sptr(smg);
    const unsigned sm_off = (lrow * GAST + lck * 8) * 2;

#define G_ISSUE(s) do {                                                        \
        cp16(smb + ((s) % 3) * GSTG_BYTES + sm_off, Gp + (s) * GBK);           \
        cp16(smb + ((s) % 3) * GSTG_BYTES + sm_off + 32, Gp + (s) * GBK + 16); \
        CP_COMMIT;                                                             \
    } while (0)

    G_ISSUE(0);
    G_ISSUE(1);

    for (int s = 0; s < NSTG; s++) {
        CP_WAIT1;
        __syncthreads();
        if (s + 2 < NSTG) G_ISSUE(s + 2);
        else              CP_COMMIT;

        const unsigned Ab = smb + (s % 3) * GSTG_BYTES;
        const unsigned Wb = Ab + 128 * GROW_B;

        // fp16 stage accumulators (2 regs per C tile)
        unsigned hc[2][4][2];

#pragma unroll
        for (int ka = 0; ka < 2; ka++) {
            unsigned af[2][4];
#pragma unroll
            for (int ma = 0; ma < 2; ma++)
                ldsm4(af[ma][0], af[ma][1], af[ma][2], af[ma][3],
                      Ab + ((wm + ma * 16 + a_r) * GAST + ka * 16 + a_k) * 2);
#pragma unroll
            for (int np = 0; np < 2; np++) {
                unsigned t0, t1, t2, t3;
                ldsm4(t0, t1, t2, t3,
                      Wb + ((wn + np * 16 + b_n) * GAST + ka * 16 + b_k) * 2);
#pragma unroll
                for (int ma = 0; ma < 2; ma++) {
                    if (ka == 0) {
                        mma16h_z(hc[ma][2 * np],     af[ma], t0, t1);
                        mma16h_z(hc[ma][2 * np + 1], af[ma], t2, t3);
                    } else {
                        mma16h(hc[ma][2 * np],     af[ma], t0, t1);
                        mma16h(hc[ma][2 * np + 1], af[ma], t2, t3);
                    }
                }
            }
        }

        // promote: fp16 stage sums -> fp32 masters
#pragma unroll
        for (int ma = 0; ma < 2; ma++)
#pragma unroll
            for (int na = 0; na < 4; na++) {
                float2 lo = __half22float2(*(__half2*)&hc[ma][na][0]);
                float2 hi = __half22float2(*(__half2*)&hc[ma][na][1]);
                acc[ma][na][0] += lo.x;
                acc[ma][na][1] += lo.y;
                acc[ma][na][2] += hi.x;
                acc[ma][na][3] += hi.y;
            }
    }

    // epilogue
#pragma unroll
    for (int ma = 0; ma < 2; ma++) {
        const int r = m0 + wm + ma * 16 + g;
#pragma unroll
        for (int na = 0; na < 4; na++) {
            const int cc = n0 + wn + na * 8 + 2 * tg;
            const float b0 = bias[cc], b1 = bias[cc + 1];
            if (OUTH) {
                __half2* O = (__half2*)p.out[z];
                O[((size_t)r * D_SZ + cc) >> 1] =
                    __floats2half2_rn((acc[ma][na][0] + b0) * oscale,
                                      (acc[ma][na][1] + b1) * oscale);
                O[((size_t)(r + 8) * D_SZ + cc) >> 1] =
                    __floats2half2_rn((acc[ma][na][2] + b0) * oscale,
                                      (acc[ma][na][3] + b1) * oscale);
            } else {
                float* O = (float*)p.out[z];
                *(float2*)&O[(size_t)r * D_SZ + cc] =
                    make_float2(acc[ma][na][0] + b0, acc[ma][na][1] + b1);
                *(float2*)&O[(size_t)(r + 8) * D_SZ + cc] =
                    make_float2(acc[ma][na][2] + b0, acc[ma][na][3] + b1);
            }
        }
    }
}

// ======================================================================
// Flash attention, fp16 mma m16n8k16 fp32-accum (unchanged — validated).
// ======================================================================
#define AST   72
#define AMAT  (64 * AST)
#define ASTG_BYTES (2 * AMAT * 2)
#define ASM_BYTES  (3 * ASTG_BYTES)

__global__ __launch_bounds__(128)
void attn_h(const __half* __restrict__ qp, const __half* __restrict__ kp,
            const __half* __restrict__ vp, __half* __restrict__ ctx)
{
    extern __shared__ __half sma[];

    const int tid  = threadIdx.x;
    const int lane = tid & 31;
    const int warp = tid >> 5;
    const int g    = lane >> 2;
    const int tg   = lane & 3;

    const int bh = blockIdx.x;
    const int b  = bh >> 4;
    const int h  = bh & 15;
    const int q0 = blockIdx.y * 64;
    const int head = h * DH;

    const int r1 = warp * 16 + g;

    const int kb_n = ((lane >> 4) & 1) * 8 + (lane & 7);
    const int kb_k = ((lane >> 3) & 1) * 8;
    const int vb_j = ((lane >> 3) & 1) * 8 + (lane & 7);
    const int vb_d = ((lane >> 4) & 1) * 8;

    const int lrow = tid >> 1;
    const int lch  = (tid & 1) * 4;

    unsigned qf[4][4];
    {
        const size_t ra = (size_t)(b * L_SZ + q0 + r1) * D_SZ + head;
        const size_t rb = ra + (size_t)8 * D_SZ;
#pragma unroll
        for (int ka = 0; ka < 4; ka++) {
            qf[ka][0] = *(const unsigned*)(qp + ra + ka * 16 + 2 * tg);
            qf[ka][1] = *(const unsigned*)(qp + rb + ka * 16 + 2 * tg);
            qf[ka][2] = *(const unsigned*)(qp + ra + ka * 16 + 8 + 2 * tg);
            qf[ka][3] = *(const unsigned*)(qp + rb + ka * 16 + 8 + 2 * tg);
        }
    }

    float of[8][4];
#pragma unroll
    for (int na = 0; na < 8; na++)
#pragma unroll
        for (int e = 0; e < 4; e++) of[na][e] = 0.0f;

    float m1 = -INFINITY, m2 = -INFINITY, l1 = 0.0f, l2 = 0.0f;

    const __half* kgp = kp + (size_t)(b * L_SZ + lrow) * D_SZ + head + lch * 8;
    const __half* vgp = vp + (size_t)(b * L_SZ + lrow) * D_SZ + head + lch * 8;
    const unsigned smb = sptr(sma);

#define A_ISSUE(t) do {                                                        \
        const unsigned st = ((t) % 3) * ASTG_BYTES;                            \
        const size_t go = (size_t)(t) * 64 * D_SZ;                             \
        unsigned sk = smb + st + (lrow * AST + lch * 8) * 2;                   \
        unsigned sv = sk + AMAT * 2;                                           \
        cp16(sk,      kgp + go);      cp16(sv,      vgp + go);                 \
        cp16(sk + 16, kgp + go + 8);  cp16(sv + 16, vgp + go + 8);             \
        cp16(sk + 32, kgp + go + 16); cp16(sv + 32, vgp + go + 16);            \
        cp16(sk + 48, kgp + go + 24); cp16(sv + 48, vgp + go + 24);            \
        CP_COMMIT;                                                             \
    } while (0)

    A_ISSUE(0);
    A_ISSUE(1);

    const int NT = L_SZ / 64;
    for (int kt = 0; kt < NT; kt++) {
        CP_WAIT1;
        __syncthreads();
        if (kt + 2 < NT) A_ISSUE(kt + 2);
        else             CP_COMMIT;

        const unsigned Kb = smb + (kt % 3) * ASTG_BYTES;
        const unsigned Vb = Kb + AMAT * 2;

        float sf[8][4];
#pragma unroll
        for (int na = 0; na < 8; na++)
#pragma unroll
            for (int e = 0; e < 4; e++) sf[na][e] = 0.0f;

#pragma unroll
        for (int ka = 0; ka < 4; ka++) {
#pragma unroll
            for (int np = 0; np < 4; np++) {
                unsigned t0, t1, t2, t3;
                ldsm4(t0, t1, t2, t3,
                      Kb + ((np * 16 + kb_n) * AST + ka * 16 + kb_k) * 2);
                mma16(sf[2 * np],     qf[ka], t0, t1);
                mma16(sf[2 * np + 1], qf[ka], t2, t3);
            }
        }

        float mx1 = -INFINITY, mx2 = -INFINITY;
#pragma unroll
        for (int na = 0; na < 8; na++) {
            mx1 = fmaxf(mx1, fmaxf(sf[na][0], sf[na][1]));
            mx2 = fmaxf(mx2, fmaxf(sf[na][2], sf[na][3]));
        }
        mx1 = fmaxf(mx1, __shfl_xor_sync(0xffffffffu, mx1, 1));
        mx1 = fmaxf(mx1, __shfl_xor_sync(0xffffffffu, mx1, 2));
        mx2 = fmaxf(mx2, __shfl_xor_sync(0xffffffffu, mx2, 1));
        mx2 = fmaxf(mx2, __shfl_xor_sync(0xffffffffu, mx2, 2));

        const float mn1 = fmaxf(m1, mx1);
        const float mn2 = fmaxf(m2, mx2);
        const float fa1 = __expf(m1 - mn1);
        const float fa2 = __expf(m2 - mn2);

        float s1 = 0.0f, s2 = 0.0f;
#pragma unroll
        for (int na = 0; na < 8; na++) {
            sf[na][0] = __expf(sf[na][0] - mn1);
            sf[na][1] = __expf(sf[na][1] - mn1);
            sf[na][2] = __expf(sf[na][2] - mn2);
            sf[na][3] = __expf(sf[na][3] - mn2);
            s1 += sf[na][0] + sf[na][1];
            s2 += sf[na][2] + sf[na][3];
        }
        s1 += __shfl_xor_sync(0xffffffffu, s1, 1);
        s1 += __shfl_xor_sync(0xffffffffu, s1, 2);
        s2 += __shfl_xor_sync(0xffffffffu, s2, 1);
        s2 += __shfl_xor_sync(0xffffffffu, s2, 2);

        l1 = l1 * fa1 + s1;  m1 = mn1;
        l2 = l2 * fa2 + s2;  m2 = mn2;

        unsigned pf[4][4];
#pragma unroll
        for (int ka = 0; ka < 4; ka++) {
            pf[ka][0] = pack_h2(sf[2*ka][0],   sf[2*ka][1]);
            pf[ka][1] = pack_h2(sf[2*ka][2],   sf[2*ka][3]);
            pf[ka][2] = pack_h2(sf[2*ka+1][0], sf[2*ka+1][1]);
            pf[ka][3] = pack_h2(sf[2*ka+1][2], sf[2*ka+1][3]);
        }

#pragma unroll
        for (int na = 0; na < 8; na++) {
            of[na][0] *= fa1; of[na][1] *= fa1;
            of[na][2] *= fa2; of[na][3] *= fa2;
        }

#pragma unroll
        for (int ka = 0; ka < 4; ka++) {
#pragma unroll
            for (int dp = 0; dp < 4; dp++) {
                unsigned t0, t1, t2, t3;
                ldsm4t(t0, t1, t2, t3,
                       Vb + ((ka * 16 + vb_j) * AST + dp * 16 + vb_d) * 2);
                mma16(of[2 * dp],     pf[ka], t0, t1);
                mma16(of[2 * dp + 1], pf[ka], t2, t3);
            }
        }
    }

    const float inv1 = 1.0f / l1;
    const float inv2 = 1.0f / l2;
    __half2* o1 = (__half2*)(ctx + (size_t)(b * L_SZ + q0 + r1) * D_SZ + head);
    __half2* o2 = (__half2*)(ctx + (size_t)(b * L_SZ + q0 + r1 + 8) * D_SZ + head);
#pragma unroll
    for (int na = 0; na < 8; na++) {
        const int cp = (na * 8 + 2 * tg) >> 1;
        o1[cp] = __floats2half2_rn(of[na][0] * inv1, of[na][1] * inv1);
        o2[cp] = __floats2half2_rn(of[na][2] * inv2, of[na][3] * inv2);
    }
}

// ======================================================================
// Launch
// ======================================================================
extern "C" void kernel_launch(void* const* d_in, const int* in_sizes, int n_in,
                              void* d_out, int out_size)
{
    const float* q   = (const float*)d_in[0];
    const float* k   = (const float*)d_in[1];
    const float* v   = (const float*)d_in[2];
    const float* w_q = (const float*)d_in[3];
    const float* b_q = (const float*)d_in[4];
    const float* w_k = (const float*)d_in[5];
    const float* b_k = (const float*)d_in[6];
    const float* w_v = (const float*)d_in[7];
    const float* b_v = (const float*)d_in[8];
    const float* w_o = (const float*)d_in[9];
    const float* b_o = (const float*)d_in[10];
    float* out = (float*)d_out;

    __half *qh, *kh, *vh, *wqh, *wkh, *wvh, *woh, *qpd, *kpd, *vpd, *ctxd;
    cudaGetSymbolAddress((void**)&qh,  g_qh);
    cudaGetSymbolAddress((void**)&kh,  g_kh);
    cudaGetSymbolAddress((void**)&vh,  g_vh);
    cudaGetSymbolAddress((void**)&wqh, g_wqh);
    cudaGetSymbolAddress((void**)&wkh, g_wkh);
    cudaGetSymbolAddress((void**)&wvh, g_wvh);
    cudaGetSymbolAddress((void**)&woh, g_woh);
    cudaGetSymbolAddress((void**)&qpd, g_qp);
    cudaGetSymbolAddress((void**)&kpd, g_kp);
    cudaGetSymbolAddress((void**)&vpd, g_vp);
    cudaGetSymbolAddress((void**)&ctxd, g_ctx);

    cudaFuncSetAttribute(gemm_h<true>,
                         cudaFuncAttributeMaxDynamicSharedMemorySize, GSM_BYTES);
    cudaFuncSetAttribute(gemm_h<false>,
                         cudaFuncAttributeMaxDynamicSharedMemorySize, GSM_BYTES);
    cudaFuncSetAttribute(attn_h,
                         cudaFuncAttributeMaxDynamicSharedMemorySize, ASM_BYTES);

    // 1) convert inputs + weights to fp16
    F2HArgs fa;
    fa.src[0] = (const float2*)q;   fa.dst[0] = (__half2*)qh;  fa.n2[0] = M_SZ * D_SZ / 2;
    fa.src[1] = (const float2*)k;   fa.dst[1] = (__half2*)kh;  fa.n2[1] = M_SZ * D_SZ / 2;
    fa.src[2] = (const float2*)v;   fa.dst[2] = (__half2*)vh;  fa.n2[2] = M_SZ * D_SZ / 2;
    fa.src[3] = (const float2*)w_q; fa.dst[3] = (__half2*)wqh; fa.n2[3] = D_SZ * D_SZ / 2;
    fa.src[4] = (const float2*)w_k; fa.dst[4] = (__half2*)wkh; fa.n2[4] = D_SZ * D_SZ / 2;
    fa.src[5] = (const float2*)w_v; fa.dst[5] = (__half2*)wvh; fa.n2[5] = D_SZ * D_SZ / 2;
    fa.src[6] = (const float2*)w_o; fa.dst[6] = (__half2*)woh; fa.n2[6] = D_SZ * D_SZ / 2;
    f2h_kernel<<<dim3(512, 7), 256>>>(fa);

    // 2) Q/K/V projections fused (z selects problem), q scaled by 1/8
    GemmBatch pb;
    pb.A[0] = qh;  pb.W[0] = wqh; pb.bias[0] = b_q; pb.out[0] = qpd; pb.oscale[0] = 0.125f;
    pb.A[1] = kh;  pb.W[1] = wkh; pb.bias[1] = b_k; pb.out[1] = kpd; pb.oscale[1] = 1.0f;
    pb.A[2] = vh;  pb.W[2] = wvh; pb.bias[2] = b_v; pb.out[2] = vpd; pb.oscale[2] = 1.0f;
    gemm_h<true><<<dim3(8, 32, 3), 512, GSM_BYTES>>>(pb);

    // 3) attention
    attn_h<<<dim3(B_SZ * H_SZ, L_SZ / 64), 128, ASM_BYTES>>>(qpd, kpd, vpd, ctxd);

    // 4) output projection (fp32 out)
    GemmBatch po;
    po.A[0] = ctxd; po.W[0] = woh; po.bias[0] = b_o; po.out[0] = out; po.oscale[0] = 1.0f;
    po.A[1] = po.A[0]; po.W[1] = po.W[0]; po.bias[1] = po.bias[0]; po.out[1] = po.out[0]; po.oscale[1] = 1.0f;
    po.A[2] = po.A[0]; po.W[2] = po.W[0]; po.bias[2] = po.bias[0]; po.out[2] = po.out[0]; po.oscale[2] = 1.0f;
    gemm_h<false><<<dim3(8, 32, 1), 512, GSM_BYTES>>>(po);
}

// round 17
// speedup vs baseline: 1.3560x; 1.3560x over previous
#include <cuda_runtime.h>
#include <cuda_fp16.h>
#include <math.h>

#define B_SZ   2
#define L_SZ   2048
#define D_SZ   1024
#define H_SZ   16
#define DH     64
#define M_SZ   (B_SZ * L_SZ)   // 4096

// ---------------- scratch (device globals) ----------------
__device__ __half g_qh[M_SZ * D_SZ];
__device__ __half g_kh[M_SZ * D_SZ];
__device__ __half g_vh[M_SZ * D_SZ];
__device__ __half g_wqh[D_SZ * D_SZ];
__device__ __half g_wkh[D_SZ * D_SZ];
__device__ __half g_wvh[D_SZ * D_SZ];
__device__ __half g_woh[D_SZ * D_SZ];
__device__ __half g_qp[M_SZ * D_SZ];
__device__ __half g_kp[M_SZ * D_SZ];
__device__ __half g_vp[M_SZ * D_SZ];
__device__ __half g_ctx[M_SZ * D_SZ];

// ---------------- PTX helpers ----------------
__device__ __forceinline__ unsigned sptr(const void* p) {
    return (unsigned)__cvta_generic_to_shared(p);
}
__device__ __forceinline__ void ldsm4(unsigned& a, unsigned& b, unsigned& c, unsigned& d,
                                      unsigned addr) {
    asm volatile("ldmatrix.sync.aligned.m8n8.x4.shared.b16 {%0,%1,%2,%3}, [%4];"
                 : "=r"(a), "=r"(b), "=r"(c), "=r"(d) : "r"(addr));
}
__device__ __forceinline__ void ldsm4t(unsigned& a, unsigned& b, unsigned& c, unsigned& d,
                                       unsigned addr) {
    asm volatile("ldmatrix.sync.aligned.m8n8.x4.trans.shared.b16 {%0,%1,%2,%3}, [%4];"
                 : "=r"(a), "=r"(b), "=r"(c), "=r"(d) : "r"(addr));
}
__device__ __forceinline__ void mma16(float* c, const unsigned* a, unsigned b0, unsigned b1) {
    asm volatile(
        "mma.sync.aligned.m16n8k16.row.col.f32.f16.f16.f32 "
        "{%0,%1,%2,%3}, {%4,%5,%6,%7}, {%8,%9}, {%0,%1,%2,%3};"
        : "+f"(c[0]), "+f"(c[1]), "+f"(c[2]), "+f"(c[3])
        : "r"(a[0]), "r"(a[1]), "r"(a[2]), "r"(a[3]), "r"(b0), "r"(b1));
}
__device__ __forceinline__ void cp16(unsigned s, const void* g) {
    asm volatile("cp.async.cg.shared.global [%0], [%1], 16;" :: "r"(s), "l"(g));
}
#define CP_COMMIT asm volatile("cp.async.commit_group;")
#define CP_WAIT1  asm volatile("cp.async.wait_group 1;")

__device__ __forceinline__ unsigned pack_h2(float a, float b) {
    __half2 h = __floats2half2_rn(a, b);
    return *(unsigned*)&h;
}

// ======================================================================
// fp32 -> fp16 conversion (7 arrays in one launch)
// ======================================================================
struct F2HArgs {
    const float2* src[7];
    __half2*      dst[7];
    int           n2[7];
};

__global__ void f2h_kernel(F2HArgs p) {
    const int seg = blockIdx.y;
    const int n2 = p.n2[seg];
    const float2* s = p.src[seg];
    __half2* d = p.dst[seg];
    for (int i = blockIdx.x * blockDim.x + threadIdx.x; i < n2;
         i += gridDim.x * blockDim.x) {
        float2 v = s[i];
        d[i] = __floats2half2_rn(v.x, v.y);
    }
}

// ======================================================================
// GEMM (NT) — exact R8 config (best measured: 342.4us total).
// CTA 128x128, 512 threads (16 warps, 4x4), warp 32x32, BK=32,
// 3-stage cp.async ring, stride-40 rows, fp32-accum mma.
// ======================================================================
#define GBK   32
#define GAST  40
#define GROW_B (GAST * 2)
#define GSTG_BYTES (256 * GROW_B)               // 20480
#define GSM_BYTES  (3 * GSTG_BYTES)             // 61440
#define NSTG  (D_SZ / GBK)                      // 32

struct GemmBatch {
    const __half* A[3];
    const __half* W[3];
    const float*  bias[3];
    void*         out[3];
    float         oscale[3];
};

template<bool OUTH>
__global__ __launch_bounds__(512, 2)
void gemm_h(GemmBatch p)
{
    extern __shared__ __half smg[];

    const int z = blockIdx.z;
    const __half* __restrict__ A = p.A[z];
    const __half* __restrict__ W = p.W[z];
    const float*  __restrict__ bias = p.bias[z];
    const float oscale = p.oscale[z];

    const int tid  = threadIdx.x;
    const int lane = tid & 31;
    const int warp = tid >> 5;
    const int wm   = (warp >> 2) * 32;
    const int wn   = (warp & 3) * 32;
    const int g    = lane >> 2;
    const int tg   = lane & 3;
    const int m0   = blockIdx.y * 128;
    const int n0   = blockIdx.x * 128;

    const int lrow = tid >> 1;
    const int lck  = tid & 1;
    const bool isW = lrow >= 128;
    const int  grow = isW ? (lrow - 128) : lrow;

    const int a_r = lane & 15;
    const int a_k = ((lane >> 4) & 1) * 8;
    const int b_n = ((lane >> 4) & 1) * 8 + (lane & 7);
    const int b_k = ((lane >> 3) & 1) * 8;

    float c[2][4][4];
#pragma unroll
    for (int i = 0; i < 2; i++)
#pragma unroll
        for (int j = 0; j < 4; j++)
#pragma unroll
            for (int e = 0; e < 4; e++) c[i][j][e] = 0.0f;

    const __half* Gp = (isW ? W + (size_t)(n0 + grow) * D_SZ
                            : A + (size_t)(m0 + grow) * D_SZ) + lck * 8;
    const unsigned smb = sptr(smg);
    const unsigned sm_off = (lrow * GAST + lck * 8) * 2;

#define G_ISSUE(s) do {                                                        \
        cp16(smb + ((s) % 3) * GSTG_BYTES + sm_off, Gp + (s) * GBK);           \
        cp16(smb + ((s) % 3) * GSTG_BYTES + sm_off + 32, Gp + (s) * GBK + 16); \
        CP_COMMIT;                                                             \
    } while (0)

    G_ISSUE(0);
    G_ISSUE(1);

    for (int s = 0; s < NSTG; s++) {
        CP_WAIT1;
        __syncthreads();
        if (s + 2 < NSTG) G_ISSUE(s + 2);
        else              CP_COMMIT;

        const unsigned Ab = smb + (s % 3) * GSTG_BYTES;
        const unsigned Wb = Ab + 128 * GROW_B;

#pragma unroll
        for (int ka = 0; ka < 2; ka++) {
            unsigned af[2][4];
#pragma unroll
            for (int ma = 0; ma < 2; ma++)
                ldsm4(af[ma][0], af[ma][1], af[ma][2], af[ma][3],
                      Ab + ((wm + ma * 16 + a_r) * GAST + ka * 16 + a_k) * 2);
#pragma unroll
            for (int np = 0; np < 2; np++) {
                unsigned t0, t1, t2, t3;
                ldsm4(t0, t1, t2, t3,
                      Wb + ((wn + np * 16 + b_n) * GAST + ka * 16 + b_k) * 2);
#pragma unroll
                for (int ma = 0; ma < 2; ma++) {
                    mma16(c[ma][2 * np],     af[ma], t0, t1);
                    mma16(c[ma][2 * np + 1], af[ma], t2, t3);
                }
            }
        }
    }

#pragma unroll
    for (int ma = 0; ma < 2; ma++) {
        const int r = m0 + wm + ma * 16 + g;
#pragma unroll
        for (int na = 0; na < 4; na++) {
            const int cc = n0 + wn + na * 8 + 2 * tg;
            const float b0 = bias[cc], b1 = bias[cc + 1];
            if (OUTH) {
                __half2* O = (__half2*)p.out[z];
                O[((size_t)r * D_SZ + cc) >> 1] =
                    __floats2half2_rn((c[ma][na][0] + b0) * oscale,
                                      (c[ma][na][1] + b1) * oscale);
                O[((size_t)(r + 8) * D_SZ + cc) >> 1] =
                    __floats2half2_rn((c[ma][na][2] + b0) * oscale,
                                      (c[ma][na][3] + b1) * oscale);
            } else {
                float* O = (float*)p.out[z];
                *(float2*)&O[(size_t)r * D_SZ + cc] =
                    make_float2(c[ma][na][0] + b0, c[ma][na][1] + b1);
                *(float2*)&O[(size_t)(r + 8) * D_SZ + cc] =
                    make_float2(c[ma][na][2] + b0, c[ma][na][3] + b1);
            }
        }
    }
}

// ======================================================================
// Flash attention — WIDENED warp tile: 32 q-rows per warp (2 row-sets).
// CTA covers 128 q-rows (grid.y = L/128), 128 threads, 4 warps.
// Each K/V ldsm now feeds 4 MMAs (2 row-sets share B frags) -> per-warp
// mma:ldsm ratio doubles; K/V gmem traffic halves (512 CTAs vs 1024).
// ======================================================================
#define AST   72
#define AMAT  (64 * AST)
#define ASTG_BYTES (2 * AMAT * 2)
#define ASM_BYTES  (3 * ASTG_BYTES)

__global__ __launch_bounds__(128)
void attn_h(const __half* __restrict__ qp, const __half* __restrict__ kp,
            const __half* __restrict__ vp, __half* __restrict__ ctx)
{
    extern __shared__ __half sma[];

    const int tid  = threadIdx.x;
    const int lane = tid & 31;
    const int warp = tid >> 5;
    const int g    = lane >> 2;
    const int tg   = lane & 3;

    const int bh = blockIdx.x;
    const int b  = bh >> 4;
    const int h  = bh & 15;
    const int q0 = blockIdx.y * 128;
    const int head = h * DH;

    const int r1 = warp * 32 + g;      // row-set 0 base; set 1 = +16

    const int kb_n = ((lane >> 4) & 1) * 8 + (lane & 7);
    const int kb_k = ((lane >> 3) & 1) * 8;
    const int vb_j = ((lane >> 3) & 1) * 8 + (lane & 7);
    const int vb_d = ((lane >> 4) & 1) * 8;

    const int lrow = tid >> 1;
    const int lch  = (tid & 1) * 4;

    // ---- Q A-fragments for both row-sets (fp16, pre-scaled by 1/8) ----
    unsigned qf[2][4][4];
#pragma unroll
    for (int s = 0; s < 2; s++) {
        const size_t ra = (size_t)(b * L_SZ + q0 + r1 + 16 * s) * D_SZ + head;
        const size_t rb = ra + (size_t)8 * D_SZ;
#pragma unroll
        for (int ka = 0; ka < 4; ka++) {
            qf[s][ka][0] = *(const unsigned*)(qp + ra + ka * 16 + 2 * tg);
            qf[s][ka][1] = *(const unsigned*)(qp + rb + ka * 16 + 2 * tg);
            qf[s][ka][2] = *(const unsigned*)(qp + ra + ka * 16 + 8 + 2 * tg);
            qf[s][ka][3] = *(const unsigned*)(qp + rb + ka * 16 + 8 + 2 * tg);
        }
    }

    float of[2][8][4];
#pragma unroll
    for (int s = 0; s < 2; s++)
#pragma unroll
        for (int na = 0; na < 8; na++)
#pragma unroll
            for (int e = 0; e < 4; e++) of[s][na][e] = 0.0f;

    float fm[2][2], fl[2][2];
#pragma unroll
    for (int s = 0; s < 2; s++) {
        fm[s][0] = -INFINITY; fm[s][1] = -INFINITY;
        fl[s][0] = 0.0f;      fl[s][1] = 0.0f;
    }

    const __half* kgp = kp + (size_t)(b * L_SZ + lrow) * D_SZ + head + lch * 8;
    const __half* vgp = vp + (size_t)(b * L_SZ + lrow) * D_SZ + head + lch * 8;
    const unsigned smb = sptr(sma);

#define A_ISSUE(t) do {                                                        \
        const unsigned st = ((t) % 3) * ASTG_BYTES;                            \
        const size_t go = (size_t)(t) * 64 * D_SZ;                             \
        unsigned sk = smb + st + (lrow * AST + lch * 8) * 2;                   \
        unsigned sv = sk + AMAT * 2;                                           \
        cp16(sk,      kgp + go);      cp16(sv,      vgp + go);                 \
        cp16(sk + 16, kgp + go + 8);  cp16(sv + 16, vgp + go + 8);             \
        cp16(sk + 32, kgp + go + 16); cp16(sv + 32, vgp + go + 16);            \
        cp16(sk + 48, kgp + go + 24); cp16(sv + 48, vgp + go + 24);            \
        CP_COMMIT;                                                             \
    } while (0)

    A_ISSUE(0);
    A_ISSUE(1);

    const int NT = L_SZ / 64;   // 32
    for (int kt = 0; kt < NT; kt++) {
        CP_WAIT1;
        __syncthreads();
        if (kt + 2 < NT) A_ISSUE(kt + 2);
        else             CP_COMMIT;

        const unsigned Kb = smb + (kt % 3) * ASTG_BYTES;
        const unsigned Vb = Kb + AMAT * 2;

        // ---- S = Qs @ K^T, both row-sets sharing K fragments ----
        float sf[2][8][4];
#pragma unroll
        for (int s = 0; s < 2; s++)
#pragma unroll
            for (int na = 0; na < 8; na++)
#pragma unroll
                for (int e = 0; e < 4; e++) sf[s][na][e] = 0.0f;

#pragma unroll
        for (int ka = 0; ka < 4; ka++) {
#pragma unroll
            for (int np = 0; np < 4; np++) {
                unsigned t0, t1, t2, t3;
                ldsm4(t0, t1, t2, t3,
                      Kb + ((np * 16 + kb_n) * AST + ka * 16 + kb_k) * 2);
                mma16(sf[0][2 * np],     qf[0][ka], t0, t1);
                mma16(sf[0][2 * np + 1], qf[0][ka], t2, t3);
                mma16(sf[1][2 * np],     qf[1][ka], t0, t1);
                mma16(sf[1][2 * np + 1], qf[1][ka], t2, t3);
            }
        }

        // ---- online softmax per row-set ----
        unsigned pf[2][4][4];
        float fa[2][2];
#pragma unroll
        for (int s = 0; s < 2; s++) {
            float mx1 = -INFINITY, mx2 = -INFINITY;
#pragma unroll
            for (int na = 0; na < 8; na++) {
                mx1 = fmaxf(mx1, fmaxf(sf[s][na][0], sf[s][na][1]));
                mx2 = fmaxf(mx2, fmaxf(sf[s][na][2], sf[s][na][3]));
            }
            mx1 = fmaxf(mx1, __shfl_xor_sync(0xffffffffu, mx1, 1));
            mx1 = fmaxf(mx1, __shfl_xor_sync(0xffffffffu, mx1, 2));
            mx2 = fmaxf(mx2, __shfl_xor_sync(0xffffffffu, mx2, 1));
            mx2 = fmaxf(mx2, __shfl_xor_sync(0xffffffffu, mx2, 2));

            const float mn1 = fmaxf(fm[s][0], mx1);
            const float mn2 = fmaxf(fm[s][1], mx2);
            fa[s][0] = __expf(fm[s][0] - mn1);
            fa[s][1] = __expf(fm[s][1] - mn2);

            float s1 = 0.0f, s2 = 0.0f;
#pragma unroll
            for (int na = 0; na < 8; na++) {
                sf[s][na][0] = __expf(sf[s][na][0] - mn1);
                sf[s][na][1] = __expf(sf[s][na][1] - mn1);
                sf[s][na][2] = __expf(sf[s][na][2] - mn2);
                sf[s][na][3] = __expf(sf[s][na][3] - mn2);
                s1 += sf[s][na][0] + sf[s][na][1];
                s2 += sf[s][na][2] + sf[s][na][3];
            }
            s1 += __shfl_xor_sync(0xffffffffu, s1, 1);
            s1 += __shfl_xor_sync(0xffffffffu, s1, 2);
            s2 += __shfl_xor_sync(0xffffffffu, s2, 1);
            s2 += __shfl_xor_sync(0xffffffffu, s2, 2);

            fl[s][0] = fl[s][0] * fa[s][0] + s1;  fm[s][0] = mn1;
            fl[s][1] = fl[s][1] * fa[s][1] + s2;  fm[s][1] = mn2;

#pragma unroll
            for (int ka = 0; ka < 4; ka++) {
                pf[s][ka][0] = pack_h2(sf[s][2*ka][0],   sf[s][2*ka][1]);
                pf[s][ka][1] = pack_h2(sf[s][2*ka][2],   sf[s][2*ka][3]);
                pf[s][ka][2] = pack_h2(sf[s][2*ka+1][0], sf[s][2*ka+1][1]);
                pf[s][ka][3] = pack_h2(sf[s][2*ka+1][2], sf[s][2*ka+1][3]);
            }

#pragma unroll
            for (int na = 0; na < 8; na++) {
                of[s][na][0] *= fa[s][0]; of[s][na][1] *= fa[s][0];
                of[s][na][2] *= fa[s][1]; of[s][na][3] *= fa[s][1];
            }
        }

        // ---- O += P @ V, both row-sets sharing V fragments ----
#pragma unroll
        for (int ka = 0; ka < 4; ka++) {
#pragma unroll
            for (int dp = 0; dp < 4; dp++) {
                unsigned t0, t1, t2, t3;
                ldsm4t(t0, t1, t2, t3,
                       Vb + ((ka * 16 + vb_j) * AST + dp * 16 + vb_d) * 2);
                mma16(of[0][2 * dp],     pf[0][ka], t0, t1);
                mma16(of[0][2 * dp + 1], pf[0][ka], t2, t3);
                mma16(of[1][2 * dp],     pf[1][ka], t0, t1);
                mma16(of[1][2 * dp + 1], pf[1][ka], t2, t3);
            }
        }
    }

    // ---- normalize + write (fp16 ctx) ----
#pragma unroll
    for (int s = 0; s < 2; s++) {
        const float inv1 = 1.0f / fl[s][0];
        const float inv2 = 1.0f / fl[s][1];
        __half2* o1 = (__half2*)(ctx + (size_t)(b * L_SZ + q0 + r1 + 16 * s) * D_SZ + head);
        __half2* o2 = (__half2*)(ctx + (size_t)(b * L_SZ + q0 + r1 + 16 * s + 8) * D_SZ + head);
#pragma unroll
        for (int na = 0; na < 8; na++) {
            const int cp = (na * 8 + 2 * tg) >> 1;
            o1[cp] = __floats2half2_rn(of[s][na][0] * inv1, of[s][na][1] * inv1);
            o2[cp] = __floats2half2_rn(of[s][na][2] * inv2, of[s][na][3] * inv2);
        }
    }
}

// ======================================================================
// Launch
// ======================================================================
extern "C" void kernel_launch(void* const* d_in, const int* in_sizes, int n_in,
                              void* d_out, int out_size)
{
    const float* q   = (const float*)d_in[0];
    const float* k   = (const float*)d_in[1];
    const float* v   = (const float*)d_in[2];
    const float* w_q = (const float*)d_in[3];
    const float* b_q = (const float*)d_in[4];
    const float* w_k = (const float*)d_in[5];
    const float* b_k = (const float*)d_in[6];
    const float* w_v = (const float*)d_in[7];
    const float* b_v = (const float*)d_in[8];
    const float* w_o = (const float*)d_in[9];
    const float* b_o = (const float*)d_in[10];
    float* out = (float*)d_out;

    __half *qh, *kh, *vh, *wqh, *wkh, *wvh, *woh, *qpd, *kpd, *vpd, *ctxd;
    cudaGetSymbolAddress((void**)&qh,  g_qh);
    cudaGetSymbolAddress((void**)&kh,  g_kh);
    cudaGetSymbolAddress((void**)&vh,  g_vh);
    cudaGetSymbolAddress((void**)&wqh, g_wqh);
    cudaGetSymbolAddress((void**)&wkh, g_wkh);
    cudaGetSymbolAddress((void**)&wvh, g_wvh);
    cudaGetSymbolAddress((void**)&woh, g_woh);
    cudaGetSymbolAddress((void**)&qpd, g_qp);
    cudaGetSymbolAddress((void**)&kpd, g_kp);
    cudaGetSymbolAddress((void**)&vpd, g_vp);
    cudaGetSymbolAddress((void**)&ctxd, g_ctx);

    cudaFuncSetAttribute(gemm_h<true>,
                         cudaFuncAttributeMaxDynamicSharedMemorySize, GSM_BYTES);
    cudaFuncSetAttribute(gemm_h<false>,
                         cudaFuncAttributeMaxDynamicSharedMemorySize, GSM_BYTES);
    cudaFuncSetAttribute(attn_h,
                         cudaFuncAttributeMaxDynamicSharedMemorySize, ASM_BYTES);

    // 1) convert inputs + weights to fp16
    F2HArgs fa;
    fa.src[0] = (const float2*)q;   fa.dst[0] = (__half2*)qh;  fa.n2[0] = M_SZ * D_SZ / 2;
    fa.src[1] = (const float2*)k;   fa.dst[1] = (__half2*)kh;  fa.n2[1] = M_SZ * D_SZ / 2;
    fa.src[2] = (const float2*)v;   fa.dst[2] = (__half2*)vh;  fa.n2[2] = M_SZ * D_SZ / 2;
    fa.src[3] = (const float2*)w_q; fa.dst[3] = (__half2*)wqh; fa.n2[3] = D_SZ * D_SZ / 2;
    fa.src[4] = (const float2*)w_k; fa.dst[4] = (__half2*)wkh; fa.n2[4] = D_SZ * D_SZ / 2;
    fa.src[5] = (const float2*)w_v; fa.dst[5] = (__half2*)wvh; fa.n2[5] = D_SZ * D_SZ / 2;
    fa.src[6] = (const float2*)w_o; fa.dst[6] = (__half2*)woh; fa.n2[6] = D_SZ * D_SZ / 2;
    f2h_kernel<<<dim3(512, 7), 256>>>(fa);

    // 2) Q/K/V projections fused (z selects problem), q scaled by 1/8
    GemmBatch pb;
    pb.A[0] = qh;  pb.W[0] = wqh; pb.bias[0] = b_q; pb.out[0] = qpd; pb.oscale[0] = 0.125f;
    pb.A[1] = kh;  pb.W[1] = wkh; pb.bias[1] = b_k; pb.out[1] = kpd; pb.oscale[1] = 1.0f;
    pb.A[2] = vh;  pb.W[2] = wvh; pb.bias[2] = b_v; pb.out[2] = vpd; pb.oscale[2] = 1.0f;
    gemm_h<true><<<dim3(8, 32, 3), 512, GSM_BYTES>>>(pb);

    // 3) attention (CTA = 128 q-rows)
    attn_h<<<dim3(B_SZ * H_SZ, L_SZ / 128), 128, ASM_BYTES>>>(qpd, kpd, vpd, ctxd);

    // 4) output projection (fp32 out)
    GemmBatch po;
    po.A[0] = ctxd; po.W[0] = woh; po.bias[0] = b_o; po.out[0] = out; po.oscale[0] = 1.0f;
    po.A[1] = po.A[0]; po.W[1] = po.W[0]; po.bias[1] = po.bias[0]; po.out[1] = po.out[0]; po.oscale[1] = 1.0f;
    po.A[2] = po.A[0]; po.W[2] = po.W[0]; po.bias[2] = po.bias[0]; po.out[2] = po.out[0]; po.oscale[2] = 1.0f;
    gemm_h<false><<<dim3(8, 32, 1), 512, GSM_BYTES>>>(po);
}